// round 1
// baseline (speedup 1.0000x reference)
#include <cuda_runtime.h>

// minGRU bidirectional scan, one CTA per (batch, channel, direction) sequence.
// x: [B, 512, L] fp32.  out: [B, 256, L] fp32.
//   forward:  h = x[b, c, :],       gate = x[b, c+128, :]     -> out[b, c, :]
//   backward: h = x[b, 256+c, :],   gate = x[b, 384+c, :]     -> out[b, 128+c, :]
//             (scan runs t = L-1 .. 0)
// Recurrence: out_t = a_t * out_{t-1} + b_t
//   a = sigmoid(-gate) = 1/(1+e^gate)
//   b = sigmoid(gate) * g(h),  g(v) = v>=0 ? 1+v : e^v

constexpr int L   = 8192;
constexpr int EPT = 16;    // elements per thread
constexpr int NT  = 512;   // threads per block (NT * EPT == L)

__device__ __forceinline__ float fast_rcp(float v) {
    float r;
    asm("rcp.approx.f32 %0, %1;" : "=f"(r) : "f"(v));
    return r;
}

__global__ __launch_bounds__(NT, 2)
void mingru_bidir_kernel(const float* __restrict__ x, float* __restrict__ out) {
    const int blk = blockIdx.x;
    const int b   = blk >> 8;        // 256 sequences per batch
    const int c2  = blk & 255;       // output channel
    const bool rev = (c2 & 128) != 0;
    const int c   = c2 & 127;

    const int hch = rev ? (256 + c) : c;
    const int gch = hch + 128;

    const float4* __restrict__ h4 = (const float4*)(x + (size_t)(b * 512 + hch) * L);
    const float4* __restrict__ g4 = (const float4*)(x + (size_t)(b * 512 + gch) * L);
    float4* __restrict__ o4 = (float4*)(out + (size_t)(b * 256 + c2) * L);

    const int tid   = threadIdx.x;
    const int lane  = tid & 31;
    const int warp  = tid >> 5;
    const int base4 = tid * (EPT / 4);   // float4 index of this thread's logical chunk

    float av[EPT], bv[EPT];

    // ---- Phase 1: load + pointwise (a_j, b_j in LOGICAL scan order) ----
    #pragma unroll
    for (int g = 0; g < EPT / 4; ++g) {
        float4 hv, gv;
        if (!rev) {
            hv = h4[base4 + g];
            gv = g4[base4 + g];
        } else {
            const int p = (L / 4) - 1 - base4 - g;   // physical float4, components reversed
            float4 ht = h4[p], gt = g4[p];
            hv = make_float4(ht.w, ht.z, ht.y, ht.x);
            gv = make_float4(gt.w, gt.z, gt.y, gt.x);
        }
        const float hh[4] = {hv.x, hv.y, hv.z, hv.w};
        const float gg[4] = {gv.x, gv.y, gv.z, gv.w};
        #pragma unroll
        for (int k = 0; k < 4; ++k) {
            const int j = g * 4 + k;
            const float eg = __expf(gg[k]);
            const float a  = fast_rcp(1.0f + eg);     // sigmoid(-gate)
            const float z  = 1.0f - a;                // sigmoid(gate)
            const float gh = (hh[k] >= 0.0f) ? (1.0f + hh[k]) : __expf(hh[k]);
            av[j] = a;
            bv[j] = z * gh;
        }
    }

    // ---- Phase 2: per-thread chunk composition (A, B): state_out = A*state_in + B
    float A = 1.0f, Bc = 0.0f;
    #pragma unroll
    for (int j = 0; j < EPT; ++j) {
        Bc = fmaf(Bc, av[j], bv[j]);
        A *= av[j];
    }

    // Warp inclusive scan with compose(earlier,(A,B)later) = (Ae*Al, Be*Al + Bl)
    #pragma unroll
    for (int off = 1; off < 32; off <<= 1) {
        const float Au = __shfl_up_sync(0xFFFFFFFFu, A,  off);
        const float Bu = __shfl_up_sync(0xFFFFFFFFu, Bc, off);
        if (lane >= off) {
            Bc = fmaf(Bu, A, Bc);   // uses OLD A (this thread's multiplier)
            A  = Au * A;
        }
    }
    // Exclusive within warp
    float Ae = __shfl_up_sync(0xFFFFFFFFu, A,  1);
    float Be = __shfl_up_sync(0xFFFFFFFFu, Bc, 1);
    if (lane == 0) { Ae = 1.0f; Be = 0.0f; }

    __shared__ float sA[NT / 32], sB[NT / 32];
    if (lane == 31) { sA[warp] = A; sB[warp] = Bc; }
    __syncthreads();

    // Warp 0 scans warp totals (exclusive)
    if (warp == 0) {
        float wa = (lane < NT / 32) ? sA[lane] : 1.0f;
        float wb = (lane < NT / 32) ? sB[lane] : 0.0f;
        #pragma unroll
        for (int off = 1; off < NT / 32; off <<= 1) {
            const float Au = __shfl_up_sync(0xFFFFFFFFu, wa, off);
            const float Bu = __shfl_up_sync(0xFFFFFFFFu, wb, off);
            if (lane >= off) {
                wb = fmaf(Bu, wa, wb);
                wa = Au * wa;
            }
        }
        const float wae = __shfl_up_sync(0xFFFFFFFFu, wa, 1);
        const float wbe = __shfl_up_sync(0xFFFFFFFFu, wb, 1);
        if (lane < NT / 32) {
            sA[lane] = (lane == 0) ? 1.0f : wae;
            sB[lane] = (lane == 0) ? 0.0f : wbe;
        }
    }
    __syncthreads();

    // Carry entering this thread's chunk (initial state is 0):
    //   state = apply(laneExcl, apply(warpExcl, 0)) = Ae * sB[warp] + Be
    float h = fmaf(sB[warp], Ae, Be);

    // ---- Phase 3: replay ----
    #pragma unroll
    for (int j = 0; j < EPT; ++j) {
        h = fmaf(av[j], h, bv[j]);
        bv[j] = h;                  // reuse bv as output staging
    }

    // ---- Store (reverse components back to physical order for rev) ----
    #pragma unroll
    for (int g = 0; g < EPT / 4; ++g) {
        if (!rev) {
            o4[base4 + g] = make_float4(bv[g*4+0], bv[g*4+1], bv[g*4+2], bv[g*4+3]);
        } else {
            o4[(L/4) - 1 - base4 - g] =
                make_float4(bv[g*4+3], bv[g*4+2], bv[g*4+1], bv[g*4+0]);
        }
    }
}

extern "C" void kernel_launch(void* const* d_in, const int* in_sizes, int n_in,
                              void* d_out, int out_size) {
    const float* x = (const float*)d_in[0];
    float* out = (float*)d_out;
    const int B = in_sizes[0] / (512 * L);   // = 8
    mingru_bidir_kernel<<<B * 256, NT>>>(x, out);
}

// round 2
// speedup vs baseline: 1.0303x; 1.0303x over previous
#include <cuda_runtime.h>

// minGRU bidirectional scan, one CTA per (batch, channel, direction) sequence.
// x: [B, 512, L] fp32.  out: [B, 256, L] fp32.
//   forward:  h = x[b, c, :],     gate = x[b, c+128, :]  -> out[b, c, :]
//   backward: h = x[b, 256+c, :], gate = x[b, 384+c, :]  -> out[b, 128+c, :] (scan t = L-1..0)
// Recurrence: out_t = a_t * out_{t-1} + b_t
//   a = sigmoid(-gate) = 1/(1+e^gate)
//   b = sigmoid(gate) * g(h),  g(v) = v>=0 ? 1+v : e^v
//
// R2: b-staging moved to (thread-private, conflict-free) shared memory to cut
// register pressure 59 -> ~42 and reach 3 CTAs/SM (75% occ).

constexpr int L   = 8192;
constexpr int EPT = 16;    // elements per thread
constexpr int NT  = 512;   // threads per block (NT * EPT == L)

__device__ __forceinline__ float fast_rcp(float v) {
    float r;
    asm("rcp.approx.f32 %0, %1;" : "=f"(r) : "f"(v));
    return r;
}

__global__ __launch_bounds__(NT, 3)
void mingru_bidir_kernel(const float* __restrict__ x, float* __restrict__ out) {
    __shared__ float sb[EPT][NT];          // per-thread b staging: sb[j][tid]
    __shared__ float sA[NT / 32], sB[NT / 32];

    const int blk = blockIdx.x;
    const int b   = blk >> 8;        // 256 sequences per batch
    const int c2  = blk & 255;       // output channel
    const bool rev = (c2 & 128) != 0;
    const int c   = c2 & 127;

    const int hch = rev ? (256 + c) : c;
    const int gch = hch + 128;

    const float4* __restrict__ h4 = (const float4*)(x + (size_t)(b * 512 + hch) * L);
    const float4* __restrict__ g4 = (const float4*)(x + (size_t)(b * 512 + gch) * L);
    float4* __restrict__ o4 = (float4*)(out + (size_t)(b * 256 + c2) * L);

    const int tid   = threadIdx.x;
    const int lane  = tid & 31;
    const int warp  = tid >> 5;
    const int base4 = tid * (EPT / 4);   // float4 index of this thread's logical chunk

    float av[EPT];
    float A = 1.0f, Bc = 0.0f;           // chunk composition, fused into phase 1

    // ---- Phase 1: load + pointwise + chunk compose (logical scan order) ----
    #pragma unroll
    for (int g = 0; g < EPT / 4; ++g) {
        float4 hv, gv;
        if (!rev) {
            hv = h4[base4 + g];
            gv = g4[base4 + g];
        } else {
            const int p = (L / 4) - 1 - base4 - g;   // physical float4, components reversed
            float4 ht = h4[p], gt = g4[p];
            hv = make_float4(ht.w, ht.z, ht.y, ht.x);
            gv = make_float4(gt.w, gt.z, gt.y, gt.x);
        }
        const float hh[4] = {hv.x, hv.y, hv.z, hv.w};
        const float gg[4] = {gv.x, gv.y, gv.z, gv.w};
        #pragma unroll
        for (int k = 0; k < 4; ++k) {
            const int j = g * 4 + k;
            const float eg = __expf(gg[k]);
            const float a  = fast_rcp(1.0f + eg);     // sigmoid(-gate)
            const float z  = 1.0f - a;                // sigmoid(gate)
            const float gh = (hh[k] >= 0.0f) ? (1.0f + hh[k]) : __expf(hh[k]);
            const float bb = z * gh;
            av[j] = a;
            sb[j][tid] = bb;
            Bc = fmaf(Bc, a, bb);
            A *= a;
        }
    }

    // ---- Phase 2: block-level scan of (A, B) affine maps ----
    // Warp inclusive scan, compose(earlier,(A,B)later) = (Ae*Al, Be*Al + Bl)
    #pragma unroll
    for (int off = 1; off < 32; off <<= 1) {
        const float Au = __shfl_up_sync(0xFFFFFFFFu, A,  off);
        const float Bu = __shfl_up_sync(0xFFFFFFFFu, Bc, off);
        if (lane >= off) {
            Bc = fmaf(Bu, A, Bc);   // uses OLD A (this thread's multiplier)
            A  = Au * A;
        }
    }
    // Exclusive within warp
    float Ae = __shfl_up_sync(0xFFFFFFFFu, A,  1);
    float Be = __shfl_up_sync(0xFFFFFFFFu, Bc, 1);
    if (lane == 0) { Ae = 1.0f; Be = 0.0f; }

    if (lane == 31) { sA[warp] = A; sB[warp] = Bc; }
    __syncthreads();

    // Warp 0 scans warp totals (exclusive)
    if (warp == 0) {
        float wa = (lane < NT / 32) ? sA[lane] : 1.0f;
        float wb = (lane < NT / 32) ? sB[lane] : 0.0f;
        #pragma unroll
        for (int off = 1; off < NT / 32; off <<= 1) {
            const float Au = __shfl_up_sync(0xFFFFFFFFu, wa, off);
            const float Bu = __shfl_up_sync(0xFFFFFFFFu, wb, off);
            if (lane >= off) {
                wb = fmaf(Bu, wa, wb);
                wa = Au * wa;
            }
        }
        const float wae = __shfl_up_sync(0xFFFFFFFFu, wa, 1);
        const float wbe = __shfl_up_sync(0xFFFFFFFFu, wb, 1);
        if (lane < NT / 32) {
            sA[lane] = (lane == 0) ? 1.0f : wae;
            sB[lane] = (lane == 0) ? 0.0f : wbe;
        }
    }
    __syncthreads();

    // Carry entering this thread's chunk (initial state is 0):
    //   state = Ae * sB[warp] + Be
    float h = fmaf(sB[warp], Ae, Be);

    // ---- Phase 3: replay + store ----
    #pragma unroll
    for (int g = 0; g < EPT / 4; ++g) {
        float o[4];
        #pragma unroll
        for (int k = 0; k < 4; ++k) {
            const int j = g * 4 + k;
            h = fmaf(av[j], h, sb[j][tid]);
            o[k] = h;
        }
        if (!rev) {
            o4[base4 + g] = make_float4(o[0], o[1], o[2], o[3]);
        } else {
            o4[(L / 4) - 1 - base4 - g] = make_float4(o[3], o[2], o[1], o[0]);
        }
    }
}

extern "C" void kernel_launch(void* const* d_in, const int* in_sizes, int n_in,
                              void* d_out, int out_size) {
    const float* x = (const float*)d_in[0];
    float* out = (float*)d_out;
    const int B = in_sizes[0] / (512 * L);   // = 8
    mingru_bidir_kernel<<<B * 256, NT>>>(x, out);
}

// round 3
// speedup vs baseline: 1.1881x; 1.1532x over previous
#include <cuda_runtime.h>
#include <cstdint>

// minGRU bidirectional scan. R3: bulk-async (TMA) smem staging.
// x: [B, 512, L] fp32 -> out: [B, 256, L] fp32.
//   out channel c2 (0..255):  rev = c2>=128, c = c2&127
//   h row = x[b, (rev?256:0)+c, :], gate row = h row + 128 channels.
// Recurrence (logical scan order; rev scans t = L-1..0):
//   out_t = a_t*out_{t-1} + b_t,  a = 1/(1+e^gate), b = (1-a)*g(h),
//   g(v) = v>=0 ? 1+v : e^v.

constexpr int L   = 8192;
constexpr int EPT = 16;
constexpr int NT  = 512;

// dynamic smem layout (floats): hbuf[L] | gbuf[L] | mbar(u64) | sA[16] | sB[16]
constexpr int SMEM_BYTES = 2 * L * 4 + 16 + 2 * 16 * 4;

__device__ __forceinline__ float fast_rcp(float v) {
    float r;
    asm("rcp.approx.f32 %0, %1;" : "=f"(r) : "f"(v));
    return r;
}

__device__ __forceinline__ void mbar_wait_parity0(uint32_t mbar) {
    uint32_t done;
    asm volatile(
        "{\n\t.reg .pred p;\n\t"
        "mbarrier.try_wait.parity.shared::cta.b64 p, [%1], 0;\n\t"
        "selp.b32 %0, 1, 0, p;\n\t}"
        : "=r"(done) : "r"(mbar) : "memory");
    while (!done) {
        asm volatile(
            "{\n\t.reg .pred p;\n\t"
            "mbarrier.try_wait.parity.shared::cta.b64 p, [%1], 0, 0x989680;\n\t"
            "selp.b32 %0, 1, 0, p;\n\t}"
            : "=r"(done) : "r"(mbar) : "memory");
    }
}

__global__ __launch_bounds__(NT, 2)
void mingru_bidir_kernel(const float* __restrict__ x, float* __restrict__ out) {
    extern __shared__ float smem[];
    float* hbuf = smem;
    float* gbuf = smem + L;
    uint64_t* mbar = (uint64_t*)(smem + 2 * L);
    float* sA = (float*)(mbar + 2);          // 16B after mbar
    float* sB = sA + 16;

    const int blk = blockIdx.x;
    const int b   = blk >> 8;
    const int c2  = blk & 255;
    const bool rev = (c2 & 128) != 0;
    const int c   = c2 & 127;
    const int hch = rev ? (256 + c) : c;

    const float* hrow = x + (size_t)(b * 512 + hch) * L;
    const float* grow = hrow + (size_t)128 * L;
    float* orow = out + (size_t)(b * 256 + c2) * L;

    const int tid  = threadIdx.x;
    const int lane = tid & 31;
    const int warp = tid >> 5;

    const uint32_t mbar_u32 = (uint32_t)__cvta_generic_to_shared(mbar);
    const uint32_t hbuf_u32 = (uint32_t)__cvta_generic_to_shared(hbuf);
    const uint32_t gbuf_u32 = (uint32_t)__cvta_generic_to_shared(gbuf);

    // ---- Async bulk load of both rows into smem ----
    if (tid == 0) {
        asm volatile("mbarrier.init.shared.b64 [%0], 1;" :: "r"(mbar_u32) : "memory");
        asm volatile("mbarrier.arrive.expect_tx.shared.b64 _, [%0], %1;"
                     :: "r"(mbar_u32), "r"(2 * L * 4) : "memory");
        asm volatile("cp.async.bulk.shared::cta.global.mbarrier::complete_tx::bytes "
                     "[%0], [%1], %2, [%3];"
                     :: "r"(hbuf_u32), "l"(hrow), "r"(L * 4), "r"(mbar_u32) : "memory");
        asm volatile("cp.async.bulk.shared::cta.global.mbarrier::complete_tx::bytes "
                     "[%0], [%1], %2, [%3];"
                     :: "r"(gbuf_u32), "l"(grow), "r"(L * 4), "r"(mbar_u32) : "memory");
    }
    __syncthreads();               // orders mbarrier.init before any try_wait
    mbar_wait_parity0(mbar_u32);

    // ---- Phase 1: rotated smem gather + pointwise + split chunk compose ----
    // Thread t owns logical elements [16t, 16t+16). Arrival s reads logical
    // j = (s + k) & 15 (k = t & 15)  -> smem index stride avoids 16-way conflicts.
    // P1 = elements k..15 (arrivals s = 0..15-k), P2 = elements 0..k-1 (rest).
    // Chunk map M = P1 o P2 : A = A1*A2, B = A1*B2 + B1.
    const int k = tid & 15;
    float av[EPT], bv[EPT];
    float A1 = 1.0f, B1 = 0.0f, A2 = 1.0f, B2 = 0.0f;

    #pragma unroll
    for (int s = 0; s < EPT; ++s) {
        const int j = (s + k) & 15;
        const int e = (tid << 4) + j;
        const int idx = rev ? (L - 1 - e) : e;
        const float hh = hbuf[idx];
        const float gg = gbuf[idx];
        const float a  = fast_rcp(1.0f + __expf(gg));
        const float gh = (hh >= 0.0f) ? (1.0f + hh) : __expf(hh);
        const float bb = (1.0f - a) * gh;
        av[s] = a;
        bv[s] = bb;
        if (s < EPT - k) { B1 = fmaf(B1, a, bb); A1 *= a; }
        else             { B2 = fmaf(B2, a, bb); A2 *= a; }
    }
    const float A  = A1 * A2;
    const float Bc0 = fmaf(A1, B2, B1);

    // ---- Phase 2: block scan of (A, B) affine maps ----
    float A_s = A, B_s = Bc0;
    #pragma unroll
    for (int off = 1; off < 32; off <<= 1) {
        const float Au = __shfl_up_sync(0xFFFFFFFFu, A_s, off);
        const float Bu = __shfl_up_sync(0xFFFFFFFFu, B_s, off);
        if (lane >= off) {
            B_s = fmaf(Bu, A_s, B_s);
            A_s = Au * A_s;
        }
    }
    float Ae = __shfl_up_sync(0xFFFFFFFFu, A_s, 1);
    float Be = __shfl_up_sync(0xFFFFFFFFu, B_s, 1);
    if (lane == 0) { Ae = 1.0f; Be = 0.0f; }

    if (lane == 31) { sA[warp] = A_s; sB[warp] = B_s; }
    __syncthreads();

    if (warp == 0) {
        float wa = (lane < NT / 32) ? sA[lane] : 1.0f;
        float wb = (lane < NT / 32) ? sB[lane] : 0.0f;
        #pragma unroll
        for (int off = 1; off < NT / 32; off <<= 1) {
            const float Au = __shfl_up_sync(0xFFFFFFFFu, wa, off);
            const float Bu = __shfl_up_sync(0xFFFFFFFFu, wb, off);
            if (lane >= off) {
                wb = fmaf(Bu, wa, wb);
                wa = Au * wa;
            }
        }
        const float wae = __shfl_up_sync(0xFFFFFFFFu, wa, 1);
        const float wbe = __shfl_up_sync(0xFFFFFFFFu, wb, 1);
        if (lane < NT / 32) {
            sA[lane] = (lane == 0) ? 1.0f : wae;
            sB[lane] = (lane == 0) ? 0.0f : wbe;
        }
    }
    __syncthreads();

    // Carry entering this thread's chunk:
    const float carry = fmaf(sB[warp], Ae, Be);

    // ---- Phase 3: replay in arrival order with two running states ----
    // s_hi runs elements k..15, seeded with state-after-P2 = A2*carry + B2.
    // s_lo runs elements 0..k-1, seeded with carry. Output overwrites hbuf.
    float s_lo = carry;
    float s_hi = fmaf(A2, carry, B2);
    #pragma unroll
    for (int s = 0; s < EPT; ++s) {
        const int j = (s + k) & 15;
        const int e = (tid << 4) + j;
        const int idx = rev ? (L - 1 - e) : e;
        float v;
        if (s < EPT - k) { s_hi = fmaf(av[s], s_hi, bv[s]); v = s_hi; }
        else             { s_lo = fmaf(av[s], s_lo, bv[s]); v = s_lo; }
        hbuf[idx] = v;
    }

    __syncthreads();

    // ---- Bulk store smem -> global ----
    if (tid == 0) {
        asm volatile("fence.proxy.async.shared::cta;" ::: "memory");
        asm volatile("cp.async.bulk.global.shared::cta.bulk_group [%0], [%1], %2;"
                     :: "l"(orow), "r"(hbuf_u32), "r"(L * 4) : "memory");
        asm volatile("cp.async.bulk.commit_group;" ::: "memory");
        asm volatile("cp.async.bulk.wait_group.read 0;" ::: "memory");
    }
}

extern "C" void kernel_launch(void* const* d_in, const int* in_sizes, int n_in,
                              void* d_out, int out_size) {
    const float* x = (const float*)d_in[0];
    float* out = (float*)d_out;
    const int B = in_sizes[0] / (512 * L);   // = 8
    cudaFuncSetAttribute(mingru_bidir_kernel,
                         cudaFuncAttributeMaxDynamicSharedMemorySize, SMEM_BYTES);
    mingru_bidir_kernel<<<B * 256, NT, SMEM_BYTES>>>(x, out);
}